// round 9
// baseline (speedup 1.0000x reference)
#include <cuda_runtime.h>
#include <cuda_bf16.h>
#include <cstdint>

#define Bz 8
#define Tz 1024
#define Dz 1024
#define Fz 4096
#define Mz (Bz * Tz)   // 8192

// ---------------------------------------------------------------------------
// Device scratch (no allocations allowed)
// ---------------------------------------------------------------------------
__device__ float g_RKV[(size_t)Mz * 3 * Dz];   // fused R|K|V, row stride 3072
__device__ float g_AO [(size_t)Mz * Dz];
__device__ float g_X1 [(size_t)Mz * Dz];
__device__ float g_H2 [(size_t)Mz * Dz];
__device__ float g_FFN[(size_t)Mz * Dz];
__device__ float g_H1 [(size_t)Mz * Fz];

__device__ __nv_bfloat16 g_xh [(size_t)Mz * Dz];
__device__ __nv_bfloat16 g_xl [(size_t)Mz * Dz];
__device__ __nv_bfloat16 g_yh [(size_t)Mz * Dz];
__device__ __nv_bfloat16 g_yl [(size_t)Mz * Dz];
__device__ __nv_bfloat16 g_x1h[(size_t)Mz * Dz];
__device__ __nv_bfloat16 g_x1l[(size_t)Mz * Dz];
__device__ __nv_bfloat16 g_s1 [(size_t)Mz * Fz];

#define NWELEM (4u * 1048576u + 2u * 4194304u)
__device__ __nv_bfloat16 g_wh[NWELEM];
__device__ __nv_bfloat16 g_wl[NWELEM];

#define OFF_WR 0u
#define OFF_WK 1048576u
#define OFF_WV 2097152u
#define OFF_WO 3145728u
#define OFF_W1 4194304u
#define OFF_W2 8388608u

// ---------------------------------------------------------------------------
// helpers
// ---------------------------------------------------------------------------
__device__ __forceinline__ uint32_t smem_u32(const void* p) {
    uint32_t a;
    asm("{ .reg .u64 t; cvta.to.shared.u64 t, %1; cvt.u32.u64 %0, t; }"
        : "=r"(a) : "l"(p));
    return a;
}

#define LDSM_X4(r0, r1, r2, r3, addr) \
    asm volatile("ldmatrix.sync.aligned.m8n8.x4.shared.b16 {%0,%1,%2,%3}, [%4];" \
                 : "=r"(r0), "=r"(r1), "=r"(r2), "=r"(r3) : "r"(addr))

#define MMA16816(d, a, b0_, b1_) \
    asm volatile("mma.sync.aligned.m16n8k16.row.col.f32.bf16.bf16.f32 " \
                 "{%0,%1,%2,%3},{%4,%5,%6,%7},{%8,%9},{%0,%1,%2,%3};" \
                 : "+f"((d)[0]), "+f"((d)[1]), "+f"((d)[2]), "+f"((d)[3]) \
                 : "r"((a)[0]), "r"((a)[1]), "r"((a)[2]), "r"((a)[3]), \
                   "r"(b0_), "r"(b1_))

#define CP16(dst, src) \
    asm volatile("cp.async.cg.shared.global [%0], [%1], 16;" \
                 :: "r"(dst), "l"((unsigned long long)__cvta_generic_to_global(src)))

// ---------------------------------------------------------------------------
// Split-bf16 mma.sync GEMM: C[M,N] = A[M,K] * B[N,K]^T (+bias), fp32 out.
// TERMS==3: Ah*Bh + Ah*Bl + Al*Bh.  TERMS==2: A*Bh + A*Bl.
// BM=128, BN=256, BK=32, 8 warps (2x4), warp tile 64x64, 3-stage cp.async.
// kk body issue order: LDSM(a4,b4) -> cp.async next stage -> MMA(Ah*Bh) with
// LDSM(c4)/LDSM(d4) folded into its shadow -> MMA(Ah*Bl) -> MMA(Al*Bh).
// ---------------------------------------------------------------------------
template <int TERMS>
__global__ __launch_bounds__(256, 1)
void mma_gemm(const __nv_bfloat16* __restrict__ Ah, const __nv_bfloat16* __restrict__ Al,
              const __nv_bfloat16* __restrict__ Bh, const __nv_bfloat16* __restrict__ Bl,
              const float* __restrict__ bias, float* __restrict__ C,
              int N, int K, int ldc)
{
    constexpr int S      = 3;
    constexpr int NA     = (TERMS == 3) ? 2 : 1;
    constexpr int MATA   = 128 * 80;
    constexpr int MATB_B = 256 * 80;
    constexpr int STAGEB = NA * MATA + 2 * MATB_B;
    constexpr int ACH    = NA * 512;
    constexpr int NCHUNK = (NA * 512 + 2048) / 256;

    extern __shared__ __align__(16) char smem[];
    const uint32_t sb = smem_u32(smem);

    const int tid  = threadIdx.x;
    const int lane = tid & 31;
    const int warp = tid >> 5;
    const int m0w  = (warp >> 2) * 64;
    const int n0w  = (warp & 3) * 64;
    const int mBlk = blockIdx.y * 128;
    const int nBlk = blockIdx.x * 256;

    const __nv_bfloat16* pA[2];
    pA[0] = Ah + (size_t)mBlk * K;
    pA[1] = (TERMS == 3) ? (Al + (size_t)mBlk * K) : pA[0];
    const __nv_bfloat16* pB[2];
    pB[0] = Bh + (size_t)nBlk * K;
    pB[1] = Bl + (size_t)nBlk * K;

    const int NT = K / 32;

    auto loadStage = [&](int kt) {
        uint32_t base = sb + (kt % S) * STAGEB;
        const int kof = kt * 32;
#pragma unroll
        for (int i = 0; i < NCHUNK; i++) {
            int c = i * 256 + tid;
            if (c < ACH) {
                int mat = c >> 9;
                int a   = c & 511;
                int r   = a >> 2;
                int c16 = a & 3;
                CP16(base + mat * MATA + r * 80 + c16 * 16,
                     pA[mat] + (size_t)r * K + kof + c16 * 8);
            } else {
                int cb  = c - ACH;
                int mat = cb >> 10;
                int bq  = cb & 1023;
                int r   = bq >> 2;
                int c16 = bq & 3;
                CP16(base + NA * MATA + mat * MATB_B + r * 80 + c16 * 16,
                     pB[mat] + (size_t)r * K + kof + c16 * 8);
            }
        }
    };

#pragma unroll
    for (int s = 0; s < S - 1; s++) {
        loadStage(s);
        asm volatile("cp.async.commit_group;");
    }

    float acc[4][8][4];
#pragma unroll
    for (int i = 0; i < 4; i++)
#pragma unroll
        for (int j = 0; j < 8; j++)
#pragma unroll
            for (int k = 0; k < 4; k++) acc[i][j][k] = 0.f;

    const uint32_t aoff = (uint32_t)((m0w + (lane & 15)) * 80 + (lane >> 4) * 16);
    const uint32_t boff = (uint32_t)((n0w + ((lane >> 4) & 1) * 8 + (lane & 7)) * 80
                                     + ((lane >> 3) & 1) * 16);
    constexpr uint32_t oAhi = 0;
    constexpr uint32_t oAlo = MATA;
    constexpr uint32_t oBhi = NA * MATA;
    constexpr uint32_t oBlo = NA * MATA + MATB_B;

    for (int kt = 0; kt < NT; kt++) {
        asm volatile("cp.async.wait_group 1;" ::: "memory");
        __syncthreads();
        const uint32_t st = sb + (kt % S) * STAGEB;
        const int nxt = kt + S - 1;

#pragma unroll
        for (int kk = 0; kk < 2; kk++) {
            const uint32_t kb = kk * 32;

            uint32_t a4[4][4], b4[4][4], c4[4][4];
            // Critical-path fragments only: Ah + Bh (8 LDSM).
#pragma unroll
            for (int mt = 0; mt < 4; mt++)
                LDSM_X4(a4[mt][0], a4[mt][1], a4[mt][2], a4[mt][3],
                        st + oAhi + aoff + mt * 1280 + kb);
#pragma unroll
            for (int q = 0; q < 4; q++)
                LDSM_X4(b4[q][0], b4[q][1], b4[q][2], b4[q][3],
                        st + oBhi + boff + q * 1280 + kb);

            // Next stage's async copies — after the critical LDSMs.
            if (kk == 0) {
                if (nxt < NT) loadStage(nxt);
                asm volatile("cp.async.commit_group;");
            }

            // MMA(Ah*Bh) first half; Bl loads fold into its shadow.
#pragma unroll
            for (int mt = 0; mt < 2; mt++)
#pragma unroll
                for (int q = 0; q < 4; q++) {
                    MMA16816(acc[mt][2 * q],     a4[mt], b4[q][0], b4[q][1]);
                    MMA16816(acc[mt][2 * q + 1], a4[mt], b4[q][2], b4[q][3]);
                }
#pragma unroll
            for (int q = 0; q < 4; q++)
                LDSM_X4(c4[q][0], c4[q][1], c4[q][2], c4[q][3],
                        st + oBlo + boff + q * 1280 + kb);

            if (TERMS == 3) {
                uint32_t d4[4][4];
                // MMA(Ah*Bh) second half; Al loads fold into its shadow.
#pragma unroll
                for (int mt = 2; mt < 4; mt++)
#pragma unroll
                    for (int q = 0; q < 4; q++) {
                        MMA16816(acc[mt][2 * q],     a4[mt], b4[q][0], b4[q][1]);
                        MMA16816(acc[mt][2 * q + 1], a4[mt], b4[q][2], b4[q][3]);
                    }
#pragma unroll
                for (int mt = 0; mt < 4; mt++)
                    LDSM_X4(d4[mt][0], d4[mt][1], d4[mt][2], d4[mt][3],
                            st + oAlo + aoff + mt * 1280 + kb);
                // MMA(Ah*Bl)
#pragma unroll
                for (int mt = 0; mt < 4; mt++)
#pragma unroll
                    for (int q = 0; q < 4; q++) {
                        MMA16816(acc[mt][2 * q],     a4[mt], c4[q][0], c4[q][1]);
                        MMA16816(acc[mt][2 * q + 1], a4[mt], c4[q][2], c4[q][3]);
                    }
                // MMA(Al*Bh)
#pragma unroll
                for (int mt = 0; mt < 4; mt++)
#pragma unroll
                    for (int q = 0; q < 4; q++) {
                        MMA16816(acc[mt][2 * q],     d4[mt], b4[q][0], b4[q][1]);
                        MMA16816(acc[mt][2 * q + 1], d4[mt], b4[q][2], b4[q][3]);
                    }
            } else {
                // MMA(Ah*Bh) second half.
#pragma unroll
                for (int mt = 2; mt < 4; mt++)
#pragma unroll
                    for (int q = 0; q < 4; q++) {
                        MMA16816(acc[mt][2 * q],     a4[mt], b4[q][0], b4[q][1]);
                        MMA16816(acc[mt][2 * q + 1], a4[mt], b4[q][2], b4[q][3]);
                    }
                // MMA(Ah*Bl)
#pragma unroll
                for (int mt = 0; mt < 4; mt++)
#pragma unroll
                    for (int q = 0; q < 4; q++) {
                        MMA16816(acc[mt][2 * q],     a4[mt], c4[q][0], c4[q][1]);
                        MMA16816(acc[mt][2 * q + 1], a4[mt], c4[q][2], c4[q][3]);
                    }
            }
        }
    }

    const int cbase = nBlk + n0w + 2 * (lane & 3);
    const int rbase = mBlk + m0w + (lane >> 2);
#pragma unroll
    for (int mt = 0; mt < 4; mt++) {
#pragma unroll
        for (int nt = 0; nt < 8; nt++) {
            int col = cbase + nt * 8;
            float b0 = 0.f, b1 = 0.f;
            if (bias) { b0 = bias[col]; b1 = bias[col + 1]; }
            int r0 = rbase + mt * 16;
            float2 v0 = make_float2(acc[mt][nt][0] + b0, acc[mt][nt][1] + b1);
            float2 v1 = make_float2(acc[mt][nt][2] + b0, acc[mt][nt][3] + b1);
            *reinterpret_cast<float2*>(C + (size_t)r0 * ldc + col)       = v0;
            *reinterpret_cast<float2*>(C + (size_t)(r0 + 8) * ldc + col) = v1;
        }
    }
}

// ---------------------------------------------------------------------------
// fp32 -> bf16 hi/lo split helpers
// ---------------------------------------------------------------------------
__device__ __forceinline__ void split_store(float4 v, __nv_bfloat16* hi,
                                            __nv_bfloat16* lo, size_t i4)
{
    __nv_bfloat16 h0 = __float2bfloat16(v.x);
    __nv_bfloat16 h1 = __float2bfloat16(v.y);
    __nv_bfloat16 h2 = __float2bfloat16(v.z);
    __nv_bfloat16 h3 = __float2bfloat16(v.w);
    reinterpret_cast<__nv_bfloat162*>(hi)[2 * i4]     = __nv_bfloat162(h0, h1);
    reinterpret_cast<__nv_bfloat162*>(hi)[2 * i4 + 1] = __nv_bfloat162(h2, h3);
    __nv_bfloat16 l0 = __float2bfloat16(v.x - __bfloat162float(h0));
    __nv_bfloat16 l1 = __float2bfloat16(v.y - __bfloat162float(h1));
    __nv_bfloat16 l2 = __float2bfloat16(v.z - __bfloat162float(h2));
    __nv_bfloat16 l3 = __float2bfloat16(v.w - __bfloat162float(h3));
    reinterpret_cast<__nv_bfloat162*>(lo)[2 * i4]     = __nv_bfloat162(l0, l1);
    reinterpret_cast<__nv_bfloat162*>(lo)[2 * i4 + 1] = __nv_bfloat162(l2, l3);
}

__global__ void split_k(const float* __restrict__ x, __nv_bfloat16* __restrict__ hi,
                        __nv_bfloat16* __restrict__ lo)
{
    int i = blockIdx.x * blockDim.x + threadIdx.x;
    split_store(reinterpret_cast<const float4*>(x)[i], hi, lo, i);
}

__global__ void split6(const float* __restrict__ wr, const float* __restrict__ wk,
                       const float* __restrict__ wv, const float* __restrict__ wo,
                       const float* __restrict__ w1, const float* __restrict__ w2,
                       __nv_bfloat16* __restrict__ hi, __nv_bfloat16* __restrict__ lo)
{
    int i = blockIdx.x * blockDim.x + threadIdx.x;
    const float* src;
    int off;
    if (i < 1048576) {
        int seg = i >> 18;
        off = i & 262143;
        src = (seg == 0) ? wr : (seg == 1) ? wk : (seg == 2) ? wv : wo;
    } else {
        int j = i - 1048576;
        off = j & 1048575;
        src = (j >> 20) ? w2 : w1;
    }
    split_store(reinterpret_cast<const float4*>(src)[off], hi, lo, i);
}

// ---------------------------------------------------------------------------
// RWKV attention scan, cp.async smem-pipelined (measured 3.96 TB/s).
// ---------------------------------------------------------------------------
__global__ __launch_bounds__(32, 4)
void attn_scan_cp(const float* __restrict__ RKV,
                  __nv_bfloat16* __restrict__ Yh, __nv_bfloat16* __restrict__ Yl)
{
    constexpr int CT = 32, ST = 4, NCH = Tz / CT;
    __shared__ float sm[ST][CT][3][32];
    const int tid = threadIdx.x;
    const int b   = blockIdx.x >> 5;
    const int cb  = (blockIdx.x & 31) * 32;
    const float* src = RKV + (size_t)b * Tz * 3072 + cb;
    const size_t baseY = (size_t)b * Tz * 1024 + cb + tid;

    auto issue = [&](int tc) {
        const float* s0 = src + (size_t)tc * CT * 3072;
        uint32_t dst = smem_u32(&sm[tc % ST][0][0][0]);
#pragma unroll
        for (int j = 0; j < 24; j++) {
            int c   = j * 32 + tid;
            int t   = c / 24;
            int rem = c - t * 24;
            int m   = rem >> 3;
            int ch4 = rem & 7;
            CP16(dst + (uint32_t)(((t * 3 + m) * 32 + ch4 * 4) * 4),
                 s0 + (size_t)t * 3072 + m * 1024 + ch4 * 4);
        }
    };

#pragma unroll
    for (int s = 0; s < ST - 1; s++) {
        issue(s);
        asm volatile("cp.async.commit_group;");
    }

    float vr = 0.f, vk = 0.f, vv = 0.f, h = 0.f;
    for (int tc = 0; tc < NCH; tc++) {
        if (tc + ST - 1 < NCH) issue(tc + ST - 1);
        asm volatile("cp.async.commit_group;");
        asm volatile("cp.async.wait_group %0;" :: "n"(ST - 1));
        __syncwarp();
        const int s = tc % ST;
#pragma unroll
        for (int t = 0; t < CT; t++) {
            float ri = sm[s][t][0][tid];
            float ki = sm[s][t][1][tid];
            float vi = sm[s][t][2][tid];

            vr += (ri - vr) * 0.5f;
            float rs = (vr >= 1.0f) ? 1.f : 0.f;
            if (rs != 0.f) vr = 0.f;
            vk += (ki - vk) * 0.5f;
            float ks = (vk >= 1.0f) ? 1.f : 0.f;
            if (ks != 0.f) vk = 0.f;
            vv += (vi - vv) * 0.5f;
            float vs = (vv >= 1.0f) ? 1.f : 0.f;
            if (vs != 0.f) vv = 0.f;

            h = h * 0.9f + ks * vs;
            float y = rs * h;
            __nv_bfloat16 yh = __float2bfloat16(y);
            size_t oy = baseY + (size_t)(tc * CT + t) * 1024;
            Yh[oy] = yh;
            Yl[oy] = __float2bfloat16(y - __bfloat162float(yh));
        }
        __syncwarp();
    }
}

// ---------------------------------------------------------------------------
// LIF scan (any width multiple of 32), cp.async smem-pipelined.
// ---------------------------------------------------------------------------
template <bool BF16OUT>
__global__ __launch_bounds__(32, 8)
void lif_scan_cp(const float* __restrict__ X, void* __restrict__ Sout, int width)
{
    constexpr int CT = 32, ST = 4, NCH = Tz / CT;
    __shared__ float sm[ST][CT][32];
    const int tid = threadIdx.x;
    const int gpb = width >> 5;
    const int b   = blockIdx.x / gpb;
    const int cb  = (blockIdx.x - b * gpb) * 32;
    const float* src = X + (size_t)b * Tz * width + cb;
    const size_t baseS = (size_t)b * Tz * width + cb + tid;
    __nv_bfloat16* Sb = (__nv_bfloat16*)Sout;
    float* Sf = (float*)Sout;

    auto issue = [&](int tc) {
        const float* s0 = src + (size_t)tc * CT * width;
        uint32_t dst = smem_u32(&sm[tc % ST][0][0]);
#pragma unroll
        for (int j = 0; j < 8; j++) {
            int c   = j * 32 + tid;
            int t   = c >> 3;
            int ch4 = c & 7;
            CP16(dst + (uint32_t)((t * 32 + ch4 * 4) * 4),
                 s0 + (size_t)t * width + ch4 * 4);
        }
    };

#pragma unroll
    for (int s = 0; s < ST - 1; s++) {
        issue(s);
        asm volatile("cp.async.commit_group;");
    }

    float v = 0.f;
    for (int tc = 0; tc < NCH; tc++) {
        if (tc + ST - 1 < NCH) issue(tc + ST - 1);
        asm volatile("cp.async.commit_group;");
        asm volatile("cp.async.wait_group %0;" :: "n"(ST - 1));
        __syncwarp();
        const int s = tc % ST;
#pragma unroll
        for (int t = 0; t < CT; t++) {
            float x = sm[s][t][tid];
            v += (x - v) * 0.5f;
            float sp = (v >= 1.0f) ? 1.f : 0.f;
            if (sp != 0.f) v = 0.f;
            size_t os = baseS + (size_t)(tc * CT + t) * width;
            if (BF16OUT) Sb[os] = __float2bfloat16(sp);
            else         Sf[os] = sp;
        }
        __syncwarp();
    }
}

// ---------------------------------------------------------------------------
// fused residual add + LayerNorm (block per row, D=1024, 256 threads)
// ---------------------------------------------------------------------------
template <bool SPLIT>
__global__ void add_ln(const float* __restrict__ A, const float* __restrict__ Bv,
                       const float* __restrict__ g, const float* __restrict__ beta,
                       float* __restrict__ O,
                       __nv_bfloat16* __restrict__ Oh, __nv_bfloat16* __restrict__ Ol)
{
    __shared__ float sm[16];
    int row = blockIdx.x;
    int tid = threadIdx.x;
    size_t base = (size_t)row * Dz;
    int c = tid * 4;

    float4 a = *reinterpret_cast<const float4*>(A  + base + c);
    float4 b = *reinterpret_cast<const float4*>(Bv + base + c);
    float x0 = a.x + b.x, x1 = a.y + b.y, x2 = a.z + b.z, x3 = a.w + b.w;

    float s  = x0 + x1 + x2 + x3;
    float ss = x0 * x0 + x1 * x1 + x2 * x2 + x3 * x3;
#pragma unroll
    for (int o = 16; o > 0; o >>= 1) {
        s  += __shfl_xor_sync(0xFFFFFFFFu, s,  o);
        ss += __shfl_xor_sync(0xFFFFFFFFu, ss, o);
    }
    int wid = tid >> 5, lane = tid & 31;
    if (lane == 0) { sm[wid] = s; sm[wid + 8] = ss; }
    __syncthreads();
    if (wid == 0) {
        float s2  = (lane < 8) ? sm[lane]     : 0.f;
        float ss2 = (lane < 8) ? sm[lane + 8] : 0.f;
#pragma unroll
        for (int o = 4; o > 0; o >>= 1) {
            s2  += __shfl_xor_sync(0xFFFFFFFFu, s2,  o);
            ss2 += __shfl_xor_sync(0xFFFFFFFFu, ss2, o);
        }
        if (lane == 0) { sm[0] = s2; sm[1] = ss2; }
    }
    __syncthreads();

    float mu  = sm[0] * (1.f / 1024.f);
    float var = sm[1] * (1.f / 1024.f) - mu * mu;
    float inv = rsqrtf(var + 1e-5f);

    float4 gg = *reinterpret_cast<const float4*>(g    + c);
    float4 bb = *reinterpret_cast<const float4*>(beta + c);
    float4 o;
    o.x = (x0 - mu) * inv * gg.x + bb.x;
    o.y = (x1 - mu) * inv * gg.y + bb.y;
    o.z = (x2 - mu) * inv * gg.z + bb.z;
    o.w = (x3 - mu) * inv * gg.w + bb.w;
    *reinterpret_cast<float4*>(O + base + c) = o;

    if (SPLIT) split_store(o, Oh, Ol, (base + c) >> 2);
}

// ---------------------------------------------------------------------------
// Host side
// ---------------------------------------------------------------------------
static void launch3(const __nv_bfloat16* Ah, const __nv_bfloat16* Al,
                    const __nv_bfloat16* Bh, const __nv_bfloat16* Bl,
                    const float* bias, float* C, int M, int N, int K, int ldc)
{
    const int SMEM = 3 * (2 * 10240 + 2 * 20480);
    cudaFuncSetAttribute(mma_gemm<3>, cudaFuncAttributeMaxDynamicSharedMemorySize, SMEM);
    mma_gemm<3><<<dim3(N / 256, M / 128), 256, SMEM>>>(Ah, Al, Bh, Bl, bias, C, N, K, ldc);
}

static void launch2(const __nv_bfloat16* Ah,
                    const __nv_bfloat16* Bh, const __nv_bfloat16* Bl,
                    const float* bias, float* C, int M, int N, int K, int ldc)
{
    const int SMEM = 3 * (10240 + 2 * 20480);
    cudaFuncSetAttribute(mma_gemm<2>, cudaFuncAttributeMaxDynamicSharedMemorySize, SMEM);
    mma_gemm<2><<<dim3(N / 256, M / 128), 256, SMEM>>>(Ah, Ah, Bh, Bl, bias, C, N, K, ldc);
}

extern "C" void kernel_launch(void* const* d_in, const int* in_sizes, int n_in,
                              void* d_out, int out_size)
{
    const float* x    = (const float*)d_in[0];
    const float* Wr   = (const float*)d_in[1];
    const float* Wk   = (const float*)d_in[2];
    const float* Wv   = (const float*)d_in[3];
    const float* Wo   = (const float*)d_in[4];
    const float* W1   = (const float*)d_in[5];
    const float* b1   = (const float*)d_in[6];
    const float* W2   = (const float*)d_in[7];
    const float* b2   = (const float*)d_in[8];
    const float* ln1g = (const float*)d_in[9];
    const float* ln1b = (const float*)d_in[10];
    const float* ln2g = (const float*)d_in[11];
    const float* ln2b = (const float*)d_in[12];
    float* out = (float*)d_out;

    float *pRKV, *pAO, *pX1, *pH1, *pH2, *pFFN;
    __nv_bfloat16 *pxh, *pxl, *pyh, *pyl, *px1h, *px1l, *ps1, *pwh, *pwl;
    cudaGetSymbolAddress((void**)&pRKV, g_RKV);
    cudaGetSymbolAddress((void**)&pAO,  g_AO);
    cudaGetSymbolAddress((void**)&pX1,  g_X1);
    cudaGetSymbolAddress((void**)&pH1,  g_H1);
    cudaGetSymbolAddress((void**)&pH2,  g_H2);
    cudaGetSymbolAddress((void**)&pFFN, g_FFN);
    cudaGetSymbolAddress((void**)&pxh,  g_xh);
    cudaGetSymbolAddress((void**)&pxl,  g_xl);
    cudaGetSymbolAddress((void**)&pyh,  g_yh);
    cudaGetSymbolAddress((void**)&pyl,  g_yl);
    cudaGetSymbolAddress((void**)&px1h, g_x1h);
    cudaGetSymbolAddress((void**)&px1l, g_x1l);
    cudaGetSymbolAddress((void**)&ps1,  g_s1);
    cudaGetSymbolAddress((void**)&pwh,  g_wh);
    cudaGetSymbolAddress((void**)&pwl,  g_wl);

    // 1) splits
    split_k<<<(Mz * Dz) / 1024, 256>>>(x, pxh, pxl);
    split6<<<(NWELEM / 4) / 256, 256>>>(Wr, Wk, Wv, Wo, W1, W2, pwh, pwl);

    // 2) fused R|K|V projection: one GEMM, N=3072
    launch3(pxh, pxl, pwh + OFF_WR, pwl + OFF_WR, nullptr, pRKV, Mz, 3 * Dz, Dz, 3 * Dz);

    // 3) RWKV attention scan -> y (bf16 hi/lo)
    attn_scan_cp<<<Bz * 32, 32>>>(pRKV, pyh, pyl);

    // 4) output projection
    launch3(pyh, pyl, pwh + OFF_WO, pwl + OFF_WO, nullptr, pAO, Mz, Dz, Dz, Dz);

    // 5) x1 = LN(x + attn_out), plus bf16 hi/lo
    add_ln<true><<<Mz, 256>>>(x, pAO, ln1g, ln1b, pX1, px1h, px1l);

    // 6) h1 = x1 @ W1^T + b1
    launch3(px1h, px1l, pwh + OFF_W1, pwl + OFF_W1, b1, pH1, Mz, Fz, Dz, Fz);

    // 7) s1 = LIF(h1) (bf16-exact spikes)
    lif_scan_cp<true><<<Bz * (Fz / 32), 32>>>(pH1, ps1, Fz);

    // 8) h2 = s1 @ W2^T + b2 (2-term)
    launch2(ps1, pwh + OFF_W2, pwl + OFF_W2, b2, pH2, Mz, Dz, Fz, Dz);

    // 9) ffn_out = LIF(h2)
    lif_scan_cp<false><<<Bz * (Dz / 32), 32>>>(pH2, pFFN, Dz);

    // 10) out = LN(x1 + ffn_out)
    add_ln<false><<<Mz, 256>>>(pX1, pFFN, ln2g, ln2b, out, nullptr, nullptr);
}

// round 10
// speedup vs baseline: 1.0678x; 1.0678x over previous
#include <cuda_runtime.h>
#include <cuda_bf16.h>
#include <cstdint>

#define Bz 8
#define Tz 1024
#define Dz 1024
#define Fz 4096
#define Mz (Bz * Tz)   // 8192

// ---------------------------------------------------------------------------
// Device scratch (no allocations allowed)
// ---------------------------------------------------------------------------
__device__ float g_RKV[(size_t)Mz * 3 * Dz];   // fused R|K|V, row stride 3072
__device__ float g_AO [(size_t)Mz * Dz];
__device__ float g_X1 [(size_t)Mz * Dz];
__device__ float g_H2 [(size_t)Mz * Dz];
__device__ float g_FFN[(size_t)Mz * Dz];
__device__ float g_H1 [(size_t)Mz * Fz];

__device__ __nv_bfloat16 g_xh [(size_t)Mz * Dz];
__device__ __nv_bfloat16 g_xl [(size_t)Mz * Dz];
__device__ __nv_bfloat16 g_yh [(size_t)Mz * Dz];
__device__ __nv_bfloat16 g_yl [(size_t)Mz * Dz];
__device__ __nv_bfloat16 g_x1h[(size_t)Mz * Dz];
__device__ __nv_bfloat16 g_x1l[(size_t)Mz * Dz];
__device__ __nv_bfloat16 g_s1 [(size_t)Mz * Fz];

#define NWELEM (4u * 1048576u + 2u * 4194304u)
__device__ __nv_bfloat16 g_wh[NWELEM];
__device__ __nv_bfloat16 g_wl[NWELEM];

#define OFF_WR 0u
#define OFF_WK 1048576u
#define OFF_WV 2097152u
#define OFF_WO 3145728u
#define OFF_W1 4194304u
#define OFF_W2 8388608u

// ---------------------------------------------------------------------------
// helpers
// ---------------------------------------------------------------------------
__device__ __forceinline__ uint32_t smem_u32(const void* p) {
    uint32_t a;
    asm("{ .reg .u64 t; cvta.to.shared.u64 t, %1; cvt.u32.u64 %0, t; }"
        : "=r"(a) : "l"(p));
    return a;
}

#define LDSM_X4(r0, r1, r2, r3, addr) \
    asm volatile("ldmatrix.sync.aligned.m8n8.x4.shared.b16 {%0,%1,%2,%3}, [%4];" \
                 : "=r"(r0), "=r"(r1), "=r"(r2), "=r"(r3) : "r"(addr))

#define MMA16816(d, a, b0_, b1_) \
    asm volatile("mma.sync.aligned.m16n8k16.row.col.f32.bf16.bf16.f32 " \
                 "{%0,%1,%2,%3},{%4,%5,%6,%7},{%8,%9},{%0,%1,%2,%3};" \
                 : "+f"((d)[0]), "+f"((d)[1]), "+f"((d)[2]), "+f"((d)[3]) \
                 : "r"((a)[0]), "r"((a)[1]), "r"((a)[2]), "r"((a)[3]), \
                   "r"(b0_), "r"(b1_))

#define CP16(dst, src) \
    asm volatile("cp.async.cg.shared.global [%0], [%1], 16;" \
                 :: "r"(dst), "l"((unsigned long long)__cvta_generic_to_global(src)))

// ---------------------------------------------------------------------------
// Split-bf16 mma.sync GEMM — R7 configuration (measured best: 1632us total).
// C[M,N] = A[M,K] * B[N,K]^T (+bias), fp32 out.
// TERMS==3: Ah*Bh + Ah*Bl + Al*Bh.  TERMS==2: A*Bh + A*Bl.
// BM=128, BN=256, BK=32, 8 warps (2x4), warp tile 64x64, 3-stage cp.async.
// kk body: all 12 LDSM batched up-front, cp.async after, then full MMA
// batches (Al LDSM between batch 1 and 2). DO NOT interleave LDSM into
// MMA halves — measured regression (R9: +112us).
// ---------------------------------------------------------------------------
template <int TERMS>
__global__ __launch_bounds__(256, 1)
void mma_gemm(const __nv_bfloat16* __restrict__ Ah, const __nv_bfloat16* __restrict__ Al,
              const __nv_bfloat16* __restrict__ Bh, const __nv_bfloat16* __restrict__ Bl,
              const float* __restrict__ bias, float* __restrict__ C,
              int N, int K, int ldc)
{
    constexpr int S      = 3;
    constexpr int NA     = (TERMS == 3) ? 2 : 1;
    constexpr int MATA   = 128 * 80;
    constexpr int MATB_B = 256 * 80;
    constexpr int STAGEB = NA * MATA + 2 * MATB_B;
    constexpr int ACH    = NA * 512;
    constexpr int NCHUNK = (NA * 512 + 2048) / 256;

    extern __shared__ __align__(16) char smem[];
    const uint32_t sb = smem_u32(smem);

    const int tid  = threadIdx.x;
    const int lane = tid & 31;
    const int warp = tid >> 5;
    const int m0w  = (warp >> 2) * 64;
    const int n0w  = (warp & 3) * 64;
    const int mBlk = blockIdx.y * 128;
    const int nBlk = blockIdx.x * 256;

    const __nv_bfloat16* pA[2];
    pA[0] = Ah + (size_t)mBlk * K;
    pA[1] = (TERMS == 3) ? (Al + (size_t)mBlk * K) : pA[0];
    const __nv_bfloat16* pB[2];
    pB[0] = Bh + (size_t)nBlk * K;
    pB[1] = Bl + (size_t)nBlk * K;

    const int NT = K / 32;

    auto loadStage = [&](int kt) {
        uint32_t base = sb + (kt % S) * STAGEB;
        const int kof = kt * 32;
#pragma unroll
        for (int i = 0; i < NCHUNK; i++) {
            int c = i * 256 + tid;
            if (c < ACH) {
                int mat = c >> 9;
                int a   = c & 511;
                int r   = a >> 2;
                int c16 = a & 3;
                CP16(base + mat * MATA + r * 80 + c16 * 16,
                     pA[mat] + (size_t)r * K + kof + c16 * 8);
            } else {
                int cb  = c - ACH;
                int mat = cb >> 10;
                int bq  = cb & 1023;
                int r   = bq >> 2;
                int c16 = bq & 3;
                CP16(base + NA * MATA + mat * MATB_B + r * 80 + c16 * 16,
                     pB[mat] + (size_t)r * K + kof + c16 * 8);
            }
        }
    };

#pragma unroll
    for (int s = 0; s < S - 1; s++) {
        loadStage(s);
        asm volatile("cp.async.commit_group;");
    }

    float acc[4][8][4];
#pragma unroll
    for (int i = 0; i < 4; i++)
#pragma unroll
        for (int j = 0; j < 8; j++)
#pragma unroll
            for (int k = 0; k < 4; k++) acc[i][j][k] = 0.f;

    const uint32_t aoff = (uint32_t)((m0w + (lane & 15)) * 80 + (lane >> 4) * 16);
    const uint32_t boff = (uint32_t)((n0w + ((lane >> 4) & 1) * 8 + (lane & 7)) * 80
                                     + ((lane >> 3) & 1) * 16);
    constexpr uint32_t oAhi = 0;
    constexpr uint32_t oAlo = MATA;
    constexpr uint32_t oBhi = NA * MATA;
    constexpr uint32_t oBlo = NA * MATA + MATB_B;

    for (int kt = 0; kt < NT; kt++) {
        asm volatile("cp.async.wait_group 1;" ::: "memory");
        __syncthreads();
        const uint32_t st = sb + (kt % S) * STAGEB;
        const int nxt = kt + S - 1;

#pragma unroll
        for (int kk = 0; kk < 2; kk++) {
            const uint32_t kb = kk * 32;

            uint32_t a4[4][4], b4[4][4], c4[4][4];
            // Load ALL of this kk's Ah, Bh, Bl fragments up-front (12 LDSM).
#pragma unroll
            for (int mt = 0; mt < 4; mt++)
                LDSM_X4(a4[mt][0], a4[mt][1], a4[mt][2], a4[mt][3],
                        st + oAhi + aoff + mt * 1280 + kb);
#pragma unroll
            for (int q = 0; q < 4; q++)
                LDSM_X4(b4[q][0], b4[q][1], b4[q][2], b4[q][3],
                        st + oBhi + boff + q * 1280 + kb);
#pragma unroll
            for (int q = 0; q < 4; q++)
                LDSM_X4(c4[q][0], c4[q][1], c4[q][2], c4[q][3],
                        st + oBlo + boff + q * 1280 + kb);

            // Next stage's async copies issue after the fragment loads.
            if (kk == 0) {
                if (nxt < NT) loadStage(nxt);
                asm volatile("cp.async.commit_group;");
            }

            // Ah * Bh
#pragma unroll
            for (int mt = 0; mt < 4; mt++)
#pragma unroll
                for (int q = 0; q < 4; q++) {
                    MMA16816(acc[mt][2 * q],     a4[mt], b4[q][0], b4[q][1]);
                    MMA16816(acc[mt][2 * q + 1], a4[mt], b4[q][2], b4[q][3]);
                }

            if (TERMS == 3) {
                // Al loads overlap the Ah*Bh MMA batch above.
                uint32_t d4[4][4];
#pragma unroll
                for (int mt = 0; mt < 4; mt++)
                    LDSM_X4(d4[mt][0], d4[mt][1], d4[mt][2], d4[mt][3],
                            st + oAlo + aoff + mt * 1280 + kb);
                // Ah * Bl
#pragma unroll
                for (int mt = 0; mt < 4; mt++)
#pragma unroll
                    for (int q = 0; q < 4; q++) {
                        MMA16816(acc[mt][2 * q],     a4[mt], c4[q][0], c4[q][1]);
                        MMA16816(acc[mt][2 * q + 1], a4[mt], c4[q][2], c4[q][3]);
                    }
                // Al * Bh
#pragma unroll
                for (int mt = 0; mt < 4; mt++)
#pragma unroll
                    for (int q = 0; q < 4; q++) {
                        MMA16816(acc[mt][2 * q],     d4[mt], b4[q][0], b4[q][1]);
                        MMA16816(acc[mt][2 * q + 1], d4[mt], b4[q][2], b4[q][3]);
                    }
            } else {
                // Ah * Bl
#pragma unroll
                for (int mt = 0; mt < 4; mt++)
#pragma unroll
                    for (int q = 0; q < 4; q++) {
                        MMA16816(acc[mt][2 * q],     a4[mt], c4[q][0], c4[q][1]);
                        MMA16816(acc[mt][2 * q + 1], a4[mt], c4[q][2], c4[q][3]);
                    }
            }
        }
    }

    const int cbase = nBlk + n0w + 2 * (lane & 3);
    const int rbase = mBlk + m0w + (lane >> 2);
#pragma unroll
    for (int mt = 0; mt < 4; mt++) {
#pragma unroll
        for (int nt = 0; nt < 8; nt++) {
            int col = cbase + nt * 8;
            float b0 = 0.f, b1 = 0.f;
            if (bias) { b0 = bias[col]; b1 = bias[col + 1]; }
            int r0 = rbase + mt * 16;
            float2 v0 = make_float2(acc[mt][nt][0] + b0, acc[mt][nt][1] + b1);
            float2 v1 = make_float2(acc[mt][nt][2] + b0, acc[mt][nt][3] + b1);
            *reinterpret_cast<float2*>(C + (size_t)r0 * ldc + col)       = v0;
            *reinterpret_cast<float2*>(C + (size_t)(r0 + 8) * ldc + col) = v1;
        }
    }
}

// ---------------------------------------------------------------------------
// fp32 -> bf16 hi/lo split helpers
// ---------------------------------------------------------------------------
__device__ __forceinline__ void split_store(float4 v, __nv_bfloat16* hi,
                                            __nv_bfloat16* lo, size_t i4)
{
    __nv_bfloat16 h0 = __float2bfloat16(v.x);
    __nv_bfloat16 h1 = __float2bfloat16(v.y);
    __nv_bfloat16 h2 = __float2bfloat16(v.z);
    __nv_bfloat16 h3 = __float2bfloat16(v.w);
    reinterpret_cast<__nv_bfloat162*>(hi)[2 * i4]     = __nv_bfloat162(h0, h1);
    reinterpret_cast<__nv_bfloat162*>(hi)[2 * i4 + 1] = __nv_bfloat162(h2, h3);
    __nv_bfloat16 l0 = __float2bfloat16(v.x - __bfloat162float(h0));
    __nv_bfloat16 l1 = __float2bfloat16(v.y - __bfloat162float(h1));
    __nv_bfloat16 l2 = __float2bfloat16(v.z - __bfloat162float(h2));
    __nv_bfloat16 l3 = __float2bfloat16(v.w - __bfloat162float(h3));
    reinterpret_cast<__nv_bfloat162*>(lo)[2 * i4]     = __nv_bfloat162(l0, l1);
    reinterpret_cast<__nv_bfloat162*>(lo)[2 * i4 + 1] = __nv_bfloat162(l2, l3);
}

__global__ void split_k(const float* __restrict__ x, __nv_bfloat16* __restrict__ hi,
                        __nv_bfloat16* __restrict__ lo)
{
    int i = blockIdx.x * blockDim.x + threadIdx.x;
    split_store(reinterpret_cast<const float4*>(x)[i], hi, lo, i);
}

__global__ void split6(const float* __restrict__ wr, const float* __restrict__ wk,
                       const float* __restrict__ wv, const float* __restrict__ wo,
                       const float* __restrict__ w1, const float* __restrict__ w2,
                       __nv_bfloat16* __restrict__ hi, __nv_bfloat16* __restrict__ lo)
{
    int i = blockIdx.x * blockDim.x + threadIdx.x;
    const float* src;
    int off;
    if (i < 1048576) {
        int seg = i >> 18;
        off = i & 262143;
        src = (seg == 0) ? wr : (seg == 1) ? wk : (seg == 2) ? wv : wo;
    } else {
        int j = i - 1048576;
        off = j & 1048575;
        src = (j >> 20) ? w2 : w1;
    }
    split_store(reinterpret_cast<const float4*>(src)[off], hi, lo, i);
}

// ---------------------------------------------------------------------------
// RWKV attention scan, cp.async smem-pipelined. ST 4->6 (deeper MLP).
// ---------------------------------------------------------------------------
__global__ __launch_bounds__(32, 2)
void attn_scan_cp(const float* __restrict__ RKV,
                  __nv_bfloat16* __restrict__ Yh, __nv_bfloat16* __restrict__ Yl)
{
    constexpr int CT = 32, ST = 6, NCH = Tz / CT;
    __shared__ float sm[ST][CT][3][32];             // 73728 B
    const int tid = threadIdx.x;
    const int b   = blockIdx.x >> 5;
    const int cb  = (blockIdx.x & 31) * 32;
    const float* src = RKV + (size_t)b * Tz * 3072 + cb;
    const size_t baseY = (size_t)b * Tz * 1024 + cb + tid;

    auto issue = [&](int tc) {
        const float* s0 = src + (size_t)tc * CT * 3072;
        uint32_t dst = smem_u32(&sm[tc % ST][0][0][0]);
#pragma unroll
        for (int j = 0; j < 24; j++) {
            int c   = j * 32 + tid;
            int t   = c / 24;
            int rem = c - t * 24;
            int m   = rem >> 3;
            int ch4 = rem & 7;
            CP16(dst + (uint32_t)(((t * 3 + m) * 32 + ch4 * 4) * 4),
                 s0 + (size_t)t * 3072 + m * 1024 + ch4 * 4);
        }
    };

#pragma unroll
    for (int s = 0; s < ST - 1; s++) {
        issue(s);
        asm volatile("cp.async.commit_group;");
    }

    float vr = 0.f, vk = 0.f, vv = 0.f, h = 0.f;
    for (int tc = 0; tc < NCH; tc++) {
        if (tc + ST - 1 < NCH) issue(tc + ST - 1);
        asm volatile("cp.async.commit_group;");
        asm volatile("cp.async.wait_group %0;" :: "n"(ST - 1));
        __syncwarp();
        const int s = tc % ST;
#pragma unroll
        for (int t = 0; t < CT; t++) {
            float ri = sm[s][t][0][tid];
            float ki = sm[s][t][1][tid];
            float vi = sm[s][t][2][tid];

            vr += (ri - vr) * 0.5f;
            float rs = (vr >= 1.0f) ? 1.f : 0.f;
            if (rs != 0.f) vr = 0.f;
            vk += (ki - vk) * 0.5f;
            float ks = (vk >= 1.0f) ? 1.f : 0.f;
            if (ks != 0.f) vk = 0.f;
            vv += (vi - vv) * 0.5f;
            float vs = (vv >= 1.0f) ? 1.f : 0.f;
            if (vs != 0.f) vv = 0.f;

            h = h * 0.9f + ks * vs;
            float y = rs * h;
            __nv_bfloat16 yh = __float2bfloat16(y);
            size_t oy = baseY + (size_t)(tc * CT + t) * 1024;
            Yh[oy] = yh;
            Yl[oy] = __float2bfloat16(y - __bfloat162float(yh));
        }
        __syncwarp();
    }
}

// ---------------------------------------------------------------------------
// LIF scan (any width multiple of 32), cp.async smem-pipelined. ST 4->6.
// ---------------------------------------------------------------------------
template <bool BF16OUT>
__global__ __launch_bounds__(32, 8)
void lif_scan_cp(const float* __restrict__ X, void* __restrict__ Sout, int width)
{
    constexpr int CT = 32, ST = 6, NCH = Tz / CT;
    __shared__ float sm[ST][CT][32];                // 24576 B
    const int tid = threadIdx.x;
    const int gpb = width >> 5;
    const int b   = blockIdx.x / gpb;
    const int cb  = (blockIdx.x - b * gpb) * 32;
    const float* src = X + (size_t)b * Tz * width + cb;
    const size_t baseS = (size_t)b * Tz * width + cb + tid;
    __nv_bfloat16* Sb = (__nv_bfloat16*)Sout;
    float* Sf = (float*)Sout;

    auto issue = [&](int tc) {
        const float* s0 = src + (size_t)tc * CT * width;
        uint32_t dst = smem_u32(&sm[tc % ST][0][0]);
#pragma unroll
        for (int j = 0; j < 8; j++) {
            int c   = j * 32 + tid;
            int t   = c >> 3;
            int ch4 = c & 7;
            CP16(dst + (uint32_t)((t * 32 + ch4 * 4) * 4),
                 s0 + (size_t)t * width + ch4 * 4);
        }
    };

#pragma unroll
    for (int s = 0; s < ST - 1; s++) {
        issue(s);
        asm volatile("cp.async.commit_group;");
    }

    float v = 0.f;
    for (int tc = 0; tc < NCH; tc++) {
        if (tc + ST - 1 < NCH) issue(tc + ST - 1);
        asm volatile("cp.async.commit_group;");
        asm volatile("cp.async.wait_group %0;" :: "n"(ST - 1));
        __syncwarp();
        const int s = tc % ST;
#pragma unroll
        for (int t = 0; t < CT; t++) {
            float x = sm[s][t][tid];
            v += (x - v) * 0.5f;
            float sp = (v >= 1.0f) ? 1.f : 0.f;
            if (sp != 0.f) v = 0.f;
            size_t os = baseS + (size_t)(tc * CT + t) * width;
            if (BF16OUT) Sb[os] = __float2bfloat16(sp);
            else         Sf[os] = sp;
        }
        __syncwarp();
    }
}

// ---------------------------------------------------------------------------
// fused residual add + LayerNorm (block per row, D=1024, 256 threads)
// ---------------------------------------------------------------------------
template <bool SPLIT>
__global__ void add_ln(const float* __restrict__ A, const float* __restrict__ Bv,
                       const float* __restrict__ g, const float* __restrict__ beta,
                       float* __restrict__ O,
                       __nv_bfloat16* __restrict__ Oh, __nv_bfloat16* __restrict__ Ol)
{
    __shared__ float sm[16];
    int row = blockIdx.x;
    int tid = threadIdx.x;
    size_t base = (size_t)row * Dz;
    int c = tid * 4;

    float4 a = *reinterpret_cast<const float4*>(A  + base + c);
    float4 b = *reinterpret_cast<const float4*>(Bv + base + c);
    float x0 = a.x + b.x, x1 = a.y + b.y, x2 = a.z + b.z, x3 = a.w + b.w;

    float s  = x0 + x1 + x2 + x3;
    float ss = x0 * x0 + x1 * x1 + x2 * x2 + x3 * x3;
#pragma unroll
    for (int o = 16; o > 0; o >>= 1) {
        s  += __shfl_xor_sync(0xFFFFFFFFu, s,  o);
        ss += __shfl_xor_sync(0xFFFFFFFFu, ss, o);
    }
    int wid = tid >> 5, lane = tid & 31;
    if (lane == 0) { sm[wid] = s; sm[wid + 8] = ss; }
    __syncthreads();
    if (wid == 0) {
        float s2  = (lane < 8) ? sm[lane]     : 0.f;
        float ss2 = (lane < 8) ? sm[lane + 8] : 0.f;
#pragma unroll
        for (int o = 4; o > 0; o >>= 1) {
            s2  += __shfl_xor_sync(0xFFFFFFFFu, s2,  o);
            ss2 += __shfl_xor_sync(0xFFFFFFFFu, ss2, o);
        }
        if (lane == 0) { sm[0] = s2; sm[1] = ss2; }
    }
    __syncthreads();

    float mu  = sm[0] * (1.f / 1024.f);
    float var = sm[1] * (1.f / 1024.f) - mu * mu;
    float inv = rsqrtf(var + 1e-5f);

    float4 gg = *reinterpret_cast<const float4*>(g    + c);
    float4 bb = *reinterpret_cast<const float4*>(beta + c);
    float4 o;
    o.x = (x0 - mu) * inv * gg.x + bb.x;
    o.y = (x1 - mu) * inv * gg.y + bb.y;
    o.z = (x2 - mu) * inv * gg.z + bb.z;
    o.w = (x3 - mu) * inv * gg.w + bb.w;
    *reinterpret_cast<float4*>(O + base + c) = o;

    if (SPLIT) split_store(o, Oh, Ol, (base + c) >> 2);
}

// ---------------------------------------------------------------------------
// Host side
// ---------------------------------------------------------------------------
static void launch3(const __nv_bfloat16* Ah, const __nv_bfloat16* Al,
                    const __nv_bfloat16* Bh, const __nv_bfloat16* Bl,
                    const float* bias, float* C, int M, int N, int K, int ldc)
{
    const int SMEM = 3 * (2 * 10240 + 2 * 20480);
    cudaFuncSetAttribute(mma_gemm<3>, cudaFuncAttributeMaxDynamicSharedMemorySize, SMEM);
    mma_gemm<3><<<dim3(N / 256, M / 128), 256, SMEM>>>(Ah, Al, Bh, Bl, bias, C, N, K, ldc);
}

static void launch2(const __nv_bfloat16* Ah,
                    const __nv_bfloat16* Bh, const __nv_bfloat16* Bl,
                    const float* bias, float* C, int M, int N, int K, int ldc)
{
    const int SMEM = 3 * (10240 + 2 * 20480);
    cudaFuncSetAttribute(mma_gemm<2>, cudaFuncAttributeMaxDynamicSharedMemorySize, SMEM);
    mma_gemm<2><<<dim3(N / 256, M / 128), 256, SMEM>>>(Ah, Ah, Bh, Bl, bias, C, N, K, ldc);
}

extern "C" void kernel_launch(void* const* d_in, const int* in_sizes, int n_in,
                              void* d_out, int out_size)
{
    const float* x    = (const float*)d_in[0];
    const float* Wr   = (const float*)d_in[1];
    const float* Wk   = (const float*)d_in[2];
    const float* Wv   = (const float*)d_in[3];
    const float* Wo   = (const float*)d_in[4];
    const float* W1   = (const float*)d_in[5];
    const float* b1   = (const float*)d_in[6];
    const float* W2   = (const float*)d_in[7];
    const float* b2   = (const float*)d_in[8];
    const float* ln1g = (const float*)d_in[9];
    const float* ln1b = (const float*)d_in[10];
    const float* ln2g = (const float*)d_in[11];
    const float* ln2b = (const float*)d_in[12];
    float* out = (float*)d_out;

    float *pRKV, *pAO, *pX1, *pH1, *pH2, *pFFN;
    __nv_bfloat16 *pxh, *pxl, *pyh, *pyl, *px1h, *px1l, *ps1, *pwh, *pwl;
    cudaGetSymbolAddress((void**)&pRKV, g_RKV);
    cudaGetSymbolAddress((void**)&pAO,  g_AO);
    cudaGetSymbolAddress((void**)&pX1,  g_X1);
    cudaGetSymbolAddress((void**)&pH1,  g_H1);
    cudaGetSymbolAddress((void**)&pH2,  g_H2);
    cudaGetSymbolAddress((void**)&pFFN, g_FFN);
    cudaGetSymbolAddress((void**)&pxh,  g_xh);
    cudaGetSymbolAddress((void**)&pxl,  g_xl);
    cudaGetSymbolAddress((void**)&pyh,  g_yh);
    cudaGetSymbolAddress((void**)&pyl,  g_yl);
    cudaGetSymbolAddress((void**)&px1h, g_x1h);
    cudaGetSymbolAddress((void**)&px1l, g_x1l);
    cudaGetSymbolAddress((void**)&ps1,  g_s1);
    cudaGetSymbolAddress((void**)&pwh,  g_wh);
    cudaGetSymbolAddress((void**)&pwl,  g_wl);

    // 1) splits
    split_k<<<(Mz * Dz) / 1024, 256>>>(x, pxh, pxl);
    split6<<<(NWELEM / 4) / 256, 256>>>(Wr, Wk, Wv, Wo, W1, W2, pwh, pwl);

    // 2) fused R|K|V projection: one GEMM, N=3072
    launch3(pxh, pxl, pwh + OFF_WR, pwl + OFF_WR, nullptr, pRKV, Mz, 3 * Dz, Dz, 3 * Dz);

    // 3) RWKV attention scan -> y (bf16 hi/lo)
    attn_scan_cp<<<Bz * 32, 32>>>(pRKV, pyh, pyl);

    // 4) output projection
    launch3(pyh, pyl, pwh + OFF_WO, pwl + OFF_WO, nullptr, pAO, Mz, Dz, Dz, Dz);

    // 5) x1 = LN(x + attn_out), plus bf16 hi/lo
    add_ln<true><<<Mz, 256>>>(x, pAO, ln1g, ln1b, pX1, px1h, px1l);

    // 6) h1 = x1 @ W1^T + b1
    launch3(px1h, px1l, pwh + OFF_W1, pwl + OFF_W1, b1, pH1, Mz, Fz, Dz, Fz);

    // 7) s1 = LIF(h1) (bf16-exact spikes)
    lif_scan_cp<true><<<Bz * (Fz / 32), 32>>>(pH1, ps1, Fz);

    // 8) h2 = s1 @ W2^T + b2 (2-term)
    launch2(ps1, pwh + OFF_W2, pwl + OFF_W2, b2, pH2, Mz, Dz, Fz, Dz);

    // 9) ffn_out = LIF(h2)
    lif_scan_cp<false><<<Bz * (Dz / 32), 32>>>(pH2, pFFN, Dz);

    // 10) out = LN(x1 + ffn_out)
    add_ln<false><<<Mz, 256>>>(pX1, pFFN, ln2g, ln2b, out, nullptr, nullptr);
}

// round 11
// speedup vs baseline: 1.0875x; 1.0184x over previous
#include <cuda_runtime.h>
#include <cuda_bf16.h>
#include <cstdint>

#define Bz 8
#define Tz 1024
#define Dz 1024
#define Fz 4096
#define Mz (Bz * Tz)   // 8192

// ---------------------------------------------------------------------------
// Device scratch (no allocations allowed)
// ---------------------------------------------------------------------------
__device__ float g_RKV[(size_t)Mz * 3 * Dz];   // fused R|K|V, row stride 3072
__device__ float g_AO [(size_t)Mz * Dz];
__device__ float g_X1 [(size_t)Mz * Dz];
__device__ float g_H2 [(size_t)Mz * Dz];
__device__ float g_FFN[(size_t)Mz * Dz];
__device__ float g_H1 [(size_t)Mz * Fz];

__device__ __nv_bfloat16 g_xh [(size_t)Mz * Dz];
__device__ __nv_bfloat16 g_xl [(size_t)Mz * Dz];
__device__ __nv_bfloat16 g_yh [(size_t)Mz * Dz];
__device__ __nv_bfloat16 g_yl [(size_t)Mz * Dz];
__device__ __nv_bfloat16 g_x1h[(size_t)Mz * Dz];
__device__ __nv_bfloat16 g_x1l[(size_t)Mz * Dz];
__device__ __nv_bfloat16 g_s1 [(size_t)Mz * Fz];

#define NWELEM (4u * 1048576u + 2u * 4194304u)
__device__ __nv_bfloat16 g_wh[NWELEM];
__device__ __nv_bfloat16 g_wl[NWELEM];

#define OFF_WR 0u
#define OFF_WK 1048576u
#define OFF_WV 2097152u
#define OFF_WO 3145728u
#define OFF_W1 4194304u
#define OFF_W2 8388608u

// ---------------------------------------------------------------------------
// helpers
// ---------------------------------------------------------------------------
__device__ __forceinline__ uint32_t smem_u32(const void* p) {
    uint32_t a;
    asm("{ .reg .u64 t; cvta.to.shared.u64 t, %1; cvt.u32.u64 %0, t; }"
        : "=r"(a) : "l"(p));
    return a;
}

#define LDSM_X4(r0, r1, r2, r3, addr) \
    asm volatile("ldmatrix.sync.aligned.m8n8.x4.shared.b16 {%0,%1,%2,%3}, [%4];" \
                 : "=r"(r0), "=r"(r1), "=r"(r2), "=r"(r3) : "r"(addr))

#define MMA16816(d, a, b0_, b1_) \
    asm volatile("mma.sync.aligned.m16n8k16.row.col.f32.bf16.bf16.f32 " \
                 "{%0,%1,%2,%3},{%4,%5,%6,%7},{%8,%9},{%0,%1,%2,%3};" \
                 : "+f"((d)[0]), "+f"((d)[1]), "+f"((d)[2]), "+f"((d)[3]) \
                 : "r"((a)[0]), "r"((a)[1]), "r"((a)[2]), "r"((a)[3]), \
                   "r"(b0_), "r"(b1_))

#define CP16(dst, src) \
    asm volatile("cp.async.cg.shared.global [%0], [%1], 16;" \
                 :: "r"(dst), "l"((unsigned long long)__cvta_generic_to_global(src)))

// ---------------------------------------------------------------------------
// Split-bf16 mma.sync GEMM: C[M,N] = A[M,K] * B[N,K]^T (+bias), fp32 out.
// TERMS==3: Ah*Bh + Ah*Bl + Al*Bh.  TERMS==2: A*Bh + A*Bl.
// BM=128, BN=256, BK=64, 8 warps (2x4), warp tile 64x64, S=2 double buffer.
// Rows padded to 144B (9x16B: conflict-free ldmatrix, r*9 mod 8 == r mod 8).
// kk body keeps the R7-measured-optimal order: 12 LDSM batched up-front,
// next-stage cp.async at kk==0, then full MMA batches (Al LDSM between
// batch 1 and 2). 16 kt iterations for K=1024 (was 32) -> half the
// barrier/wait overhead.
// ---------------------------------------------------------------------------
template <int TERMS>
__global__ __launch_bounds__(256, 1)
void mma_gemm(const __nv_bfloat16* __restrict__ Ah, const __nv_bfloat16* __restrict__ Al,
              const __nv_bfloat16* __restrict__ Bh, const __nv_bfloat16* __restrict__ Bl,
              const float* __restrict__ bias, float* __restrict__ C,
              int N, int K, int ldc)
{
    constexpr int S      = 2;
    constexpr int NA     = (TERMS == 3) ? 2 : 1;
    constexpr int ROWB   = 144;                    // 128B data + 16B pad
    constexpr int MATA   = 128 * ROWB;             // 18432
    constexpr int MATB_B = 256 * ROWB;             // 36864
    constexpr int STAGEB = NA * MATA + 2 * MATB_B;
    constexpr int ACH    = NA * 1024;              // A 16B-chunks per stage
    constexpr int NCHUNK = (NA * 1024 + 4096) / 256;

    extern __shared__ __align__(16) char smem[];
    const uint32_t sb = smem_u32(smem);

    const int tid  = threadIdx.x;
    const int lane = tid & 31;
    const int warp = tid >> 5;
    const int m0w  = (warp >> 2) * 64;
    const int n0w  = (warp & 3) * 64;
    const int mBlk = blockIdx.y * 128;
    const int nBlk = blockIdx.x * 256;

    const __nv_bfloat16* pA[2];
    pA[0] = Ah + (size_t)mBlk * K;
    pA[1] = (TERMS == 3) ? (Al + (size_t)mBlk * K) : pA[0];
    const __nv_bfloat16* pB[2];
    pB[0] = Bh + (size_t)nBlk * K;
    pB[1] = Bl + (size_t)nBlk * K;

    const int NT = K / 64;

    auto loadStage = [&](int kt) {
        uint32_t base = sb + (kt & 1) * STAGEB;
        const int kof = kt * 64;
#pragma unroll
        for (int i = 0; i < NCHUNK; i++) {
            int c = i * 256 + tid;
            if (c < ACH) {
                int mat = c >> 10;
                int a   = c & 1023;
                int r   = a >> 3;
                int c16 = a & 7;
                CP16(base + mat * MATA + r * ROWB + c16 * 16,
                     pA[mat] + (size_t)r * K + kof + c16 * 8);
            } else {
                int cb  = c - ACH;
                int mat = cb >> 11;
                int bq  = cb & 2047;
                int r   = bq >> 3;
                int c16 = bq & 7;
                CP16(base + NA * MATA + mat * MATB_B + r * ROWB + c16 * 16,
                     pB[mat] + (size_t)r * K + kof + c16 * 8);
            }
        }
    };

    // prologue: stage 0 only
    loadStage(0);
    asm volatile("cp.async.commit_group;");

    float acc[4][8][4];
#pragma unroll
    for (int i = 0; i < 4; i++)
#pragma unroll
        for (int j = 0; j < 8; j++)
#pragma unroll
            for (int k = 0; k < 4; k++) acc[i][j][k] = 0.f;

    const uint32_t aoff = (uint32_t)((m0w + (lane & 15)) * ROWB + (lane >> 4) * 16);
    const uint32_t boff = (uint32_t)((n0w + ((lane >> 4) & 1) * 8 + (lane & 7)) * ROWB
                                     + ((lane >> 3) & 1) * 16);
    constexpr uint32_t oAhi = 0;
    constexpr uint32_t oAlo = MATA;
    constexpr uint32_t oBhi = NA * MATA;
    constexpr uint32_t oBlo = NA * MATA + MATB_B;
    constexpr uint32_t MTS  = 16 * ROWB;           // 16-row stride = 2304

    for (int kt = 0; kt < NT; kt++) {
        asm volatile("cp.async.wait_group 0;" ::: "memory");
        __syncthreads();
        const uint32_t st = sb + (kt & 1) * STAGEB;
        const int nxt = kt + 1;

#pragma unroll
        for (int kk = 0; kk < 4; kk++) {
            const uint32_t kb = kk * 32;

            uint32_t a4[4][4], b4[4][4], c4[4][4];
            // Load ALL of this kk's Ah, Bh, Bl fragments up-front (12 LDSM).
#pragma unroll
            for (int mt = 0; mt < 4; mt++)
                LDSM_X4(a4[mt][0], a4[mt][1], a4[mt][2], a4[mt][3],
                        st + oAhi + aoff + mt * MTS + kb);
#pragma unroll
            for (int q = 0; q < 4; q++)
                LDSM_X4(b4[q][0], b4[q][1], b4[q][2], b4[q][3],
                        st + oBhi + boff + q * MTS + kb);
#pragma unroll
            for (int q = 0; q < 4; q++)
                LDSM_X4(c4[q][0], c4[q][1], c4[q][2], c4[q][3],
                        st + oBlo + boff + q * MTS + kb);

            // Next stage's async copies issue after the fragment loads;
            // ~3 kk of MMA shadow remain to cover the copy latency.
            if (kk == 0 && nxt < NT) {
                loadStage(nxt);
                asm volatile("cp.async.commit_group;");
            }

            // Ah * Bh
#pragma unroll
            for (int mt = 0; mt < 4; mt++)
#pragma unroll
                for (int q = 0; q < 4; q++) {
                    MMA16816(acc[mt][2 * q],     a4[mt], b4[q][0], b4[q][1]);
                    MMA16816(acc[mt][2 * q + 1], a4[mt], b4[q][2], b4[q][3]);
                }

            if (TERMS == 3) {
                // Al loads overlap the Ah*Bh MMA batch above.
                uint32_t d4[4][4];
#pragma unroll
                for (int mt = 0; mt < 4; mt++)
                    LDSM_X4(d4[mt][0], d4[mt][1], d4[mt][2], d4[mt][3],
                            st + oAlo + aoff + mt * MTS + kb);
                // Ah * Bl
#pragma unroll
                for (int mt = 0; mt < 4; mt++)
#pragma unroll
                    for (int q = 0; q < 4; q++) {
                        MMA16816(acc[mt][2 * q],     a4[mt], c4[q][0], c4[q][1]);
                        MMA16816(acc[mt][2 * q + 1], a4[mt], c4[q][2], c4[q][3]);
                    }
                // Al * Bh
#pragma unroll
                for (int mt = 0; mt < 4; mt++)
#pragma unroll
                    for (int q = 0; q < 4; q++) {
                        MMA16816(acc[mt][2 * q],     d4[mt], b4[q][0], b4[q][1]);
                        MMA16816(acc[mt][2 * q + 1], d4[mt], b4[q][2], b4[q][3]);
                    }
            } else {
                // Ah * Bl
#pragma unroll
                for (int mt = 0; mt < 4; mt++)
#pragma unroll
                    for (int q = 0; q < 4; q++) {
                        MMA16816(acc[mt][2 * q],     a4[mt], c4[q][0], c4[q][1]);
                        MMA16816(acc[mt][2 * q + 1], a4[mt], c4[q][2], c4[q][3]);
                    }
            }
        }
    }

    const int cbase = nBlk + n0w + 2 * (lane & 3);
    const int rbase = mBlk + m0w + (lane >> 2);
#pragma unroll
    for (int mt = 0; mt < 4; mt++) {
#pragma unroll
        for (int nt = 0; nt < 8; nt++) {
            int col = cbase + nt * 8;
            float b0 = 0.f, b1 = 0.f;
            if (bias) { b0 = bias[col]; b1 = bias[col + 1]; }
            int r0 = rbase + mt * 16;
            float2 v0 = make_float2(acc[mt][nt][0] + b0, acc[mt][nt][1] + b1);
            float2 v1 = make_float2(acc[mt][nt][2] + b0, acc[mt][nt][3] + b1);
            *reinterpret_cast<float2*>(C + (size_t)r0 * ldc + col)       = v0;
            *reinterpret_cast<float2*>(C + (size_t)(r0 + 8) * ldc + col) = v1;
        }
    }
}

// ---------------------------------------------------------------------------
// fp32 -> bf16 hi/lo split helpers
// ---------------------------------------------------------------------------
__device__ __forceinline__ void split_store(float4 v, __nv_bfloat16* hi,
                                            __nv_bfloat16* lo, size_t i4)
{
    __nv_bfloat16 h0 = __float2bfloat16(v.x);
    __nv_bfloat16 h1 = __float2bfloat16(v.y);
    __nv_bfloat16 h2 = __float2bfloat16(v.z);
    __nv_bfloat16 h3 = __float2bfloat16(v.w);
    reinterpret_cast<__nv_bfloat162*>(hi)[2 * i4]     = __nv_bfloat162(h0, h1);
    reinterpret_cast<__nv_bfloat162*>(hi)[2 * i4 + 1] = __nv_bfloat162(h2, h3);
    __nv_bfloat16 l0 = __float2bfloat16(v.x - __bfloat162float(h0));
    __nv_bfloat16 l1 = __float2bfloat16(v.y - __bfloat162float(h1));
    __nv_bfloat16 l2 = __float2bfloat16(v.z - __bfloat162float(h2));
    __nv_bfloat16 l3 = __float2bfloat16(v.w - __bfloat162float(h3));
    reinterpret_cast<__nv_bfloat162*>(lo)[2 * i4]     = __nv_bfloat162(l0, l1);
    reinterpret_cast<__nv_bfloat162*>(lo)[2 * i4 + 1] = __nv_bfloat162(l2, l3);
}

__global__ void split_k(const float* __restrict__ x, __nv_bfloat16* __restrict__ hi,
                        __nv_bfloat16* __restrict__ lo)
{
    int i = blockIdx.x * blockDim.x + threadIdx.x;
    split_store(reinterpret_cast<const float4*>(x)[i], hi, lo, i);
}

__global__ void split6(const float* __restrict__ wr, const float* __restrict__ wk,
                       const float* __restrict__ wv, const float* __restrict__ wo,
                       const float* __restrict__ w1, const float* __restrict__ w2,
                       __nv_bfloat16* __restrict__ hi, __nv_bfloat16* __restrict__ lo)
{
    int i = blockIdx.x * blockDim.x + threadIdx.x;
    const float* src;
    int off;
    if (i < 1048576) {
        int seg = i >> 18;
        off = i & 262143;
        src = (seg == 0) ? wr : (seg == 1) ? wk : (seg == 2) ? wv : wo;
    } else {
        int j = i - 1048576;
        off = j & 1048575;
        src = (j >> 20) ? w2 : w1;
    }
    split_store(reinterpret_cast<const float4*>(src)[off], hi, lo, i);
}

// ---------------------------------------------------------------------------
// RWKV attention scan, cp.async smem-pipelined (measured 3.9 TB/s).
// ---------------------------------------------------------------------------
__global__ __launch_bounds__(32, 2)
void attn_scan_cp(const float* __restrict__ RKV,
                  __nv_bfloat16* __restrict__ Yh, __nv_bfloat16* __restrict__ Yl)
{
    constexpr int CT = 32, ST = 6, NCH = Tz / CT;
    __shared__ float sm[ST][CT][3][32];
    const int tid = threadIdx.x;
    const int b   = blockIdx.x >> 5;
    const int cb  = (blockIdx.x & 31) * 32;
    const float* src = RKV + (size_t)b * Tz * 3072 + cb;
    const size_t baseY = (size_t)b * Tz * 1024 + cb + tid;

    auto issue = [&](int tc) {
        const float* s0 = src + (size_t)tc * CT * 3072;
        uint32_t dst = smem_u32(&sm[tc % ST][0][0][0]);
#pragma unroll
        for (int j = 0; j < 24; j++) {
            int c   = j * 32 + tid;
            int t   = c / 24;
            int rem = c - t * 24;
            int m   = rem >> 3;
            int ch4 = rem & 7;
            CP16(dst + (uint32_t)(((t * 3 + m) * 32 + ch4 * 4) * 4),
                 s0 + (size_t)t * 3072 + m * 1024 + ch4 * 4);
        }
    };

#pragma unroll
    for (int s = 0; s < ST - 1; s++) {
        issue(s);
        asm volatile("cp.async.commit_group;");
    }

    float vr = 0.f, vk = 0.f, vv = 0.f, h = 0.f;
    for (int tc = 0; tc < NCH; tc++) {
        if (tc + ST - 1 < NCH) issue(tc + ST - 1);
        asm volatile("cp.async.commit_group;");
        asm volatile("cp.async.wait_group %0;" :: "n"(ST - 1));
        __syncwarp();
        const int s = tc % ST;
#pragma unroll
        for (int t = 0; t < CT; t++) {
            float ri = sm[s][t][0][tid];
            float ki = sm[s][t][1][tid];
            float vi = sm[s][t][2][tid];

            vr += (ri - vr) * 0.5f;
            float rs = (vr >= 1.0f) ? 1.f : 0.f;
            if (rs != 0.f) vr = 0.f;
            vk += (ki - vk) * 0.5f;
            float ks = (vk >= 1.0f) ? 1.f : 0.f;
            if (ks != 0.f) vk = 0.f;
            vv += (vi - vv) * 0.5f;
            float vs = (vv >= 1.0f) ? 1.f : 0.f;
            if (vs != 0.f) vv = 0.f;

            h = h * 0.9f + ks * vs;
            float y = rs * h;
            __nv_bfloat16 yh = __float2bfloat16(y);
            size_t oy = baseY + (size_t)(tc * CT + t) * 1024;
            Yh[oy] = yh;
            Yl[oy] = __float2bfloat16(y - __bfloat162float(yh));
        }
        __syncwarp();
    }
}

// ---------------------------------------------------------------------------
// LIF scan (any width multiple of 32), cp.async smem-pipelined.
// ---------------------------------------------------------------------------
template <bool BF16OUT>
__global__ __launch_bounds__(32, 8)
void lif_scan_cp(const float* __restrict__ X, void* __restrict__ Sout, int width)
{
    constexpr int CT = 32, ST = 6, NCH = Tz / CT;
    __shared__ float sm[ST][CT][32];
    const int tid = threadIdx.x;
    const int gpb = width >> 5;
    const int b   = blockIdx.x / gpb;
    const int cb  = (blockIdx.x - b * gpb) * 32;
    const float* src = X + (size_t)b * Tz * width + cb;
    const size_t baseS = (size_t)b * Tz * width + cb + tid;
    __nv_bfloat16* Sb = (__nv_bfloat16*)Sout;
    float* Sf = (float*)Sout;

    auto issue = [&](int tc) {
        const float* s0 = src + (size_t)tc * CT * width;
        uint32_t dst = smem_u32(&sm[tc % ST][0][0]);
#pragma unroll
        for (int j = 0; j < 8; j++) {
            int c   = j * 32 + tid;
            int t   = c >> 3;
            int ch4 = c & 7;
            CP16(dst + (uint32_t)((t * 32 + ch4 * 4) * 4),
                 s0 + (size_t)t * width + ch4 * 4);
        }
    };

#pragma unroll
    for (int s = 0; s < ST - 1; s++) {
        issue(s);
        asm volatile("cp.async.commit_group;");
    }

    float v = 0.f;
    for (int tc = 0; tc < NCH; tc++) {
        if (tc + ST - 1 < NCH) issue(tc + ST - 1);
        asm volatile("cp.async.commit_group;");
        asm volatile("cp.async.wait_group %0;" :: "n"(ST - 1));
        __syncwarp();
        const int s = tc % ST;
#pragma unroll
        for (int t = 0; t < CT; t++) {
            float x = sm[s][t][tid];
            v += (x - v) * 0.5f;
            float sp = (v >= 1.0f) ? 1.f : 0.f;
            if (sp != 0.f) v = 0.f;
            size_t os = baseS + (size_t)(tc * CT + t) * width;
            if (BF16OUT) Sb[os] = __float2bfloat16(sp);
            else         Sf[os] = sp;
        }
        __syncwarp();
    }
}

// ---------------------------------------------------------------------------
// fused residual add + LayerNorm (block per row, D=1024, 256 threads)
// ---------------------------------------------------------------------------
template <bool SPLIT>
__global__ void add_ln(const float* __restrict__ A, const float* __restrict__ Bv,
                       const float* __restrict__ g, const float* __restrict__ beta,
                       float* __restrict__ O,
                       __nv_bfloat16* __restrict__ Oh, __nv_bfloat16* __restrict__ Ol)
{
    __shared__ float sm[16];
    int row = blockIdx.x;
    int tid = threadIdx.x;
    size_t base = (size_t)row * Dz;
    int c = tid * 4;

    float4 a = *reinterpret_cast<const float4*>(A  + base + c);
    float4 b = *reinterpret_cast<const float4*>(Bv + base + c);
    float x0 = a.x + b.x, x1 = a.y + b.y, x2 = a.z + b.z, x3 = a.w + b.w;

    float s  = x0 + x1 + x2 + x3;
    float ss = x0 * x0 + x1 * x1 + x2 * x2 + x3 * x3;
#pragma unroll
    for (int o = 16; o > 0; o >>= 1) {
        s  += __shfl_xor_sync(0xFFFFFFFFu, s,  o);
        ss += __shfl_xor_sync(0xFFFFFFFFu, ss, o);
    }
    int wid = tid >> 5, lane = tid & 31;
    if (lane == 0) { sm[wid] = s; sm[wid + 8] = ss; }
    __syncthreads();
    if (wid == 0) {
        float s2  = (lane < 8) ? sm[lane]     : 0.f;
        float ss2 = (lane < 8) ? sm[lane + 8] : 0.f;
#pragma unroll
        for (int o = 4; o > 0; o >>= 1) {
            s2  += __shfl_xor_sync(0xFFFFFFFFu, s2,  o);
            ss2 += __shfl_xor_sync(0xFFFFFFFFu, ss2, o);
        }
        if (lane == 0) { sm[0] = s2; sm[1] = ss2; }
    }
    __syncthreads();

    float mu  = sm[0] * (1.f / 1024.f);
    float var = sm[1] * (1.f / 1024.f) - mu * mu;
    float inv = rsqrtf(var + 1e-5f);

    float4 gg = *reinterpret_cast<const float4*>(g    + c);
    float4 bb = *reinterpret_cast<const float4*>(beta + c);
    float4 o;
    o.x = (x0 - mu) * inv * gg.x + bb.x;
    o.y = (x1 - mu) * inv * gg.y + bb.y;
    o.z = (x2 - mu) * inv * gg.z + bb.z;
    o.w = (x3 - mu) * inv * gg.w + bb.w;
    *reinterpret_cast<float4*>(O + base + c) = o;

    if (SPLIT) split_store(o, Oh, Ol, (base + c) >> 2);
}

// ---------------------------------------------------------------------------
// Host side
// ---------------------------------------------------------------------------
static void launch3(const __nv_bfloat16* Ah, const __nv_bfloat16* Al,
                    const __nv_bfloat16* Bh, const __nv_bfloat16* Bl,
                    const float* bias, float* C, int M, int N, int K, int ldc)
{
    const int SMEM = 2 * (2 * 18432 + 2 * 36864);   // 221184
    cudaFuncSetAttribute(mma_gemm<3>, cudaFuncAttributeMaxDynamicSharedMemorySize, SMEM);
    mma_gemm<3><<<dim3(N / 256, M / 128), 256, SMEM>>>(Ah, Al, Bh, Bl, bias, C, N, K, ldc);
}

static void launch2(const __nv_bfloat16* Ah,
                    const __nv_bfloat16* Bh, const __nv_bfloat16* Bl,
                    const float* bias, float* C, int M, int N, int K, int ldc)
{
    const int SMEM = 2 * (18432 + 2 * 36864);       // 184320
    cudaFuncSetAttribute(mma_gemm<2>, cudaFuncAttributeMaxDynamicSharedMemorySize, SMEM);
    mma_gemm<2><<<dim3(N / 256, M / 128), 256, SMEM>>>(Ah, Ah, Bh, Bl, bias, C, N, K, ldc);
}

extern "C" void kernel_launch(void* const* d_in, const int* in_sizes, int n_in,
                              void* d_out, int out_size)
{
    const float* x    = (const float*)d_in[0];
    const float* Wr   = (const float*)d_in[1];
    const float* Wk   = (const float*)d_in[2];
    const float* Wv   = (const float*)d_in[3];
    const float* Wo   = (const float*)d_in[4];
    const float* W1   = (const float*)d_in[5];
    const float* b1   = (const float*)d_in[6];
    const float* W2   = (const float*)d_in[7];
    const float* b2   = (const float*)d_in[8];
    const float* ln1g = (const float*)d_in[9];
    const float* ln1b = (const float*)d_in[10];
    const float* ln2g = (const float*)d_in[11];
    const float* ln2b = (const float*)d_in[12];
    float* out = (float*)d_out;

    float *pRKV, *pAO, *pX1, *pH1, *pH2, *pFFN;
    __nv_bfloat16 *pxh, *pxl, *pyh, *pyl, *px1h, *px1l, *ps1, *pwh, *pwl;
    cudaGetSymbolAddress((void**)&pRKV, g_RKV);
    cudaGetSymbolAddress((void**)&pAO,  g_AO);
    cudaGetSymbolAddress((void**)&pX1,  g_X1);
    cudaGetSymbolAddress((void**)&pH1,  g_H1);
    cudaGetSymbolAddress((void**)&pH2,  g_H2);
    cudaGetSymbolAddress((void**)&pFFN, g_FFN);
    cudaGetSymbolAddress((void**)&pxh,  g_xh);
    cudaGetSymbolAddress((void**)&pxl,  g_xl);
    cudaGetSymbolAddress((void**)&pyh,  g_yh);
    cudaGetSymbolAddress((void**)&pyl,  g_yl);
    cudaGetSymbolAddress((void**)&px1h, g_x1h);
    cudaGetSymbolAddress((void**)&px1l, g_x1l);
    cudaGetSymbolAddress((void**)&ps1,  g_s1);
    cudaGetSymbolAddress((void**)&pwh,  g_wh);
    cudaGetSymbolAddress((void**)&pwl,  g_wl);

    // 1) splits
    split_k<<<(Mz * Dz) / 1024, 256>>>(x, pxh, pxl);
    split6<<<(NWELEM / 4) / 256, 256>>>(Wr, Wk, Wv, Wo, W1, W2, pwh, pwl);

    // 2) fused R|K|V projection: one GEMM, N=3072
    launch3(pxh, pxl, pwh + OFF_WR, pwl + OFF_WR, nullptr, pRKV, Mz, 3 * Dz, Dz, 3 * Dz);

    // 3) RWKV attention scan -> y (bf16 hi/lo)
    attn_scan_cp<<<Bz * 32, 32>>>(pRKV, pyh, pyl);

    // 4) output projection
    launch3(pyh, pyl, pwh + OFF_WO, pwl + OFF_WO, nullptr, pAO, Mz, Dz, Dz, Dz);

    // 5) x1 = LN(x + attn_out), plus bf16 hi/lo
    add_ln<true><<<Mz, 256>>>(x, pAO, ln1g, ln1b, pX1, px1h, px1l);

    // 6) h1 = x1 @ W1^T + b1
    launch3(px1h, px1l, pwh + OFF_W1, pwl + OFF_W1, b1, pH1, Mz, Fz, Dz, Fz);

    // 7) s1 = LIF(h1) (bf16-exact spikes)
    lif_scan_cp<true><<<Bz * (Fz / 32), 32>>>(pH1, ps1, Fz);

    // 8) h2 = s1 @ W2^T + b2 (2-term)
    launch2(ps1, pwh + OFF_W2, pwl + OFF_W2, b2, pH2, Mz, Dz, Fz, Dz);

    // 9) ffn_out = LIF(h2)
    lif_scan_cp<false><<<Bz * (Dz / 32), 32>>>(pH2, pFFN, Dz);

    // 10) out = LN(x1 + ffn_out)
    add_ln<false><<<Mz, 256>>>(pX1, pFFN, ln2g, ln2b, out, nullptr, nullptr);
}